// round 17
// baseline (speedup 1.0000x reference)
#include <cuda_runtime.h>
#include <cuda_fp16.h>

// Shifted-window attention (UniMatch/Swin), B=8, H=96, W=128, C=128, NS=4.
// SINGLE kernel: K/V staged as f32 via cp.async (double-pipelined), converted
// to f16 in-loop (off critical path), fp16 mma.m16n8k16 f32-acc, fused
// softmax+PV, mask-aware block skipping. No prep pass, no gmem scratch.

namespace {
constexpr int H_IMG = 96, W_IMG = 128, C_DIM = 128;
constexpr int WSH = 24, WSW = 32, SHF = 12, SWF = 16;
constexpr int BM = 256, BN = 64;
constexpr int NKT = 12, NQT = 3;
constexpr int STRB = 272;                    // f16 smem row stride bytes (136 halfs)
constexpr int STRF = 512;                    // f32 staging row stride bytes
constexpr int SM_Q  = 0;                     // 256 rows f16        (69632 B)
constexpr int SM_KV = SM_Q + BM * STRB;      // K[64]+V[64] f16     (34816 B)
constexpr int SM_KF = SM_KV + 2 * BN * STRB; // K staging f32       (32768 B)
constexpr int SM_VF = SM_KF + BN * STRF;     // V staging f32       (32768 B)
constexpr int SMEM_BYTES = SM_VF + BN * STRF;    // 169984 -> 1 CTA/SM
constexpr float ISL2  = 0.12751744154f;      // log2(e)/sqrt(128)
constexpr float MASKB = -144.26950409f;      // -100*log2(e)
}

// token index within window -> global token row (roll(-12,-16) + split; self-inverse)
__device__ __forceinline__ int grow_idx(int b, int wy, int wx, int t) {
    int r = t >> 5, cc = t & 31;
    int hi = wy * WSH + r + SHF; if (hi >= H_IMG) hi -= H_IMG;
    int wi = wx * WSW + cc + SWF; if (wi >= W_IMG) wi -= W_IMG;
    return b * (H_IMG * W_IMG) + hi * W_IMG + wi;
}

__device__ __forceinline__ unsigned h2u(__half2 h) { return *reinterpret_cast<unsigned*>(&h); }
__device__ __forceinline__ float ex2f(float x) {
    float r; asm("ex2.approx.f32 %0, %1;" : "=f"(r) : "f"(x)); return r;
}

__device__ __forceinline__ void mma_f16(float& c0, float& c1, float& c2, float& c3,
                                        unsigned a0, unsigned a1, unsigned a2, unsigned a3,
                                        unsigned b0, unsigned b1) {
    asm volatile(
        "mma.sync.aligned.m16n8k16.row.col.f32.f16.f16.f32 "
        "{%0,%1,%2,%3}, {%4,%5,%6,%7}, {%8,%9}, {%0,%1,%2,%3};"
        : "+f"(c0), "+f"(c1), "+f"(c2), "+f"(c3)
        : "r"(a0), "r"(a1), "r"(a2), "r"(a3), "r"(b0), "r"(b1));
}
#define LDSM_X4(r0, r1, r2, r3, addr)                                            \
    asm volatile("ldmatrix.sync.aligned.m8n8.x4.shared.b16 {%0,%1,%2,%3}, [%4];" \
                 : "=r"(r0), "=r"(r1), "=r"(r2), "=r"(r3) : "r"(addr))
#define LDSM_X4_T(r0, r1, r2, r3, addr)                                                \
    asm volatile("ldmatrix.sync.aligned.m8n8.x4.trans.shared.b16 {%0,%1,%2,%3}, [%4];" \
                 : "=r"(r0), "=r"(r1), "=r"(r2), "=r"(r3) : "r"(addr))
#define CP16(dst, src) \
    asm volatile("cp.async.cg.shared.global [%0], [%1], 16;" :: "r"(dst), "l"(src))
#define CP_COMMIT() asm volatile("cp.async.commit_group;" ::: "memory")
#define CP_WAIT(n)  asm volatile("cp.async.wait_group %0;" :: "n"(n) : "memory")

// issue f32 staging cp.async for one K/V tile (tile base token = kb)
__device__ __forceinline__ void stage_kv(unsigned sb, const float* __restrict__ k,
                                         const float* __restrict__ v,
                                         int b, int wy, int wx, int kb, int tid) {
    #pragma unroll
    for (int i = 0; i < 8; ++i) {
        int idx = i * 256 + tid;               // 2048 16B chunks per array
        int row = idx >> 5, c16 = idx & 31;    // 32 chunks per 512B f32 row
        int grow = grow_idx(b, wy, wx, kb + row);
        const float* kp = k + (size_t)grow * C_DIM + c16 * 4;
        const float* vp = v + (size_t)grow * C_DIM + c16 * 4;
        CP16(sb + SM_KF + row * STRF + c16 * 16, kp);
        CP16(sb + SM_VF + row * STRF + c16 * 16, vp);
    }
    CP_COMMIT();
}

__global__ __launch_bounds__(256, 1)
void swin_attn_f16(const float* __restrict__ q, const float* __restrict__ k,
                   const float* __restrict__ v, float* __restrict__ out) {
    extern __shared__ char smem[];
    const unsigned sb = (unsigned)__cvta_generic_to_shared(smem);

    const int tid  = threadIdx.x;
    const int lane = tid & 31;
    const int warp = tid >> 5;          // 0..7, owns q-rows 32*warp..+31 (2 A-tiles)
    const int lr   = lane >> 2;
    const int lc   = lane & 3;

    const int win  = blockIdx.y;
    const int b    = win >> 4;
    const int widx = win & 15;
    const int wy   = widx >> 2;
    const int wx   = widx & 3;
    const int qbase = blockIdx.x * BM;
    const bool wy3 = (wy == 3);
    const bool wx3 = (wx == 3);

    // ---- prologue: stage KV tile 0 (f32), then Q f32 -> f16 ----
    stage_kv(sb, k, v, b, wy, wx, 0, tid);

    #pragma unroll
    for (int s = 0; s < 32; ++s) {
        int local = warp * 32 + s;
        int row = grow_idx(b, wy, wx, qbase + local);
        float4 val = reinterpret_cast<const float4*>(q + (size_t)row * C_DIM)[lane];
        *reinterpret_cast<uint2*>(smem + SM_Q + local * STRB + lane * 8) =
            make_uint2(h2u(__floats2half2_rn(val.x, val.y)),
                       h2u(__floats2half2_rn(val.z, val.w)));
    }

    // q-region row id: one per warp (all 32 tokens of a warp share a window-row)
    const int qrh_all = wy3 ? ((((qbase + warp * 32) >> 5) < 12) ? 1 : 2) : 0;
    // CTA-uniform region? (q-block spans window-rows qbase/32 .. +7)
    const int qr0 = qbase >> 5;
    const bool cta_uniform = (qr0 + 7 < 12) || (qr0 >= 12);
    const int qrh_cta = (qr0 < 12) ? 1 : 2;    // valid when cta_uniform

    // ldmatrix lane-address offsets (bytes); single K/V f16 buffer
    const unsigned q_lds0 = sb + SM_Q + (warp * 32 + (lane & 15)) * STRB + (lane & 16);
    const unsigned q_lds1 = q_lds0 + 16 * STRB;
    const unsigned k_lds  = sb + SM_KV +
        ((lane & 7) + ((lane & 16) >> 1)) * STRB + (lane & 8) * 2;
    const unsigned v_lds  = sb + SM_KV + BN * STRB +
        ((lane & 7) + (lane & 8)) * STRB + (lane & 16);

    float o[2][16][4];
    #pragma unroll
    for (int at = 0; at < 2; ++at)
        #pragma unroll
        for (int t = 0; t < 16; ++t)
            o[at][t][0] = o[at][t][1] = o[at][t][2] = o[at][t][3] = 0.f;
    float lsum[2][2] = {{0.f, 0.f}, {0.f, 0.f}};

    for (int kt = 0; kt < NKT; ++kt) {
        CP_WAIT(0);
        __syncthreads();   // staging(kt) visible; prior MMA done (f16 buffer free)

        // CTA-wide skip (wy==3, uniform region, mismatched kt): no convert, no MMA
        const bool cta_skip = wy3 && cta_uniform && ((((kt < 6) ? 1 : 2)) != qrh_cta);

        if (!cta_skip) {
            // ---- convert staging f32 -> f16 smem (K then V) ----
            #pragma unroll
            for (int i = 0; i < 4; ++i) {
                int idx = i * 256 + tid;           // 1024 16B f16 chunks
                int row = idx >> 4, c16 = idx & 15;
                const float4* s4 =
                    reinterpret_cast<const float4*>(smem + SM_KF + row * STRF + c16 * 32);
                float4 a = s4[0], c = s4[1];
                *reinterpret_cast<uint4*>(smem + SM_KV + row * STRB + c16 * 16) =
                    make_uint4(h2u(__floats2half2_rn(a.x, a.y)),
                               h2u(__floats2half2_rn(a.z, a.w)),
                               h2u(__floats2half2_rn(c.x, c.y)),
                               h2u(__floats2half2_rn(c.z, c.w)));
            }
            #pragma unroll
            for (int i = 0; i < 4; ++i) {
                int idx = i * 256 + tid;
                int row = idx >> 4, c16 = idx & 15;
                const float4* s4 =
                    reinterpret_cast<const float4*>(smem + SM_VF + row * STRF + c16 * 32);
                float4 a = s4[0], c = s4[1];
                *reinterpret_cast<uint4*>(smem + SM_KV + (BN + row) * STRB + c16 * 16) =
                    make_uint4(h2u(__floats2half2_rn(a.x, a.y)),
                               h2u(__floats2half2_rn(a.z, a.w)),
                               h2u(__floats2half2_rn(c.x, c.y)),
                               h2u(__floats2half2_rn(c.z, c.w)));
            }
        }
        __syncthreads();   // f16 ready; staging free for next prefetch

        if (kt < NKT - 1)
            stage_kv(sb, k, v, b, wy, wx, (kt + 1) * BN, tid);   // overlaps MMA below

        // warp-level skip (wy==3 mixed block): all P of this kt exactly 0
        const bool skip_kt = cta_skip || (wy3 && (((kt < 6) ? 1 : 2) != qrh_all));
        if (!skip_kt) {
            // ---- S = Q K^T. wx==3: at=0 needs even tp only, at=1 odd tp. ----
            float acc[2][8][4];
            #pragma unroll
            for (int at = 0; at < 2; ++at)
                #pragma unroll
                for (int t = 0; t < 8; ++t)
                    acc[at][t][0] = acc[at][t][1] = acc[at][t][2] = acc[at][t][3] = 0.f;

            #pragma unroll
            for (int kk = 0; kk < 8; ++kk) {
                unsigned a00, a01, a02, a03, a10, a11, a12, a13;
                LDSM_X4(a00, a01, a02, a03, q_lds0 + kk * 32);
                LDSM_X4(a10, a11, a12, a13, q_lds1 + kk * 32);
                #pragma unroll
                for (int tp = 0; tp < 4; ++tp) {
                    unsigned b0, b1, b2, b3;
                    LDSM_X4(b0, b1, b2, b3, k_lds + tp * (16 * STRB) + kk * 32);
                    if (!wx3 || (tp & 1) == 0) {
                        mma_f16(acc[0][2*tp][0], acc[0][2*tp][1], acc[0][2*tp][2], acc[0][2*tp][3],
                                a00, a01, a02, a03, b0, b1);
                        mma_f16(acc[0][2*tp+1][0], acc[0][2*tp+1][1], acc[0][2*tp+1][2], acc[0][2*tp+1][3],
                                a00, a01, a02, a03, b2, b3);
                    }
                    if (!wx3 || (tp & 1) == 1) {
                        mma_f16(acc[1][2*tp][0], acc[1][2*tp][1], acc[1][2*tp][2], acc[1][2*tp][3],
                                a10, a11, a12, a13, b0, b1);
                        mma_f16(acc[1][2*tp+1][0], acc[1][2*tp+1][1], acc[1][2*tp+1][2], acc[1][2*tp+1][3],
                                a10, a11, a12, a13, b2, b3);
                    }
                }
            }

            // ---- FUSED softmax + PV per 16-token chunk s (tp==s).
            //      wx==3: chunk s feeds only at = s&1. ----
            const int krhA = wy3 ? (((2 * kt)     < 12) ? 1 : 2) : 0;
            const int krhB = wy3 ? (((2 * kt + 1) < 12) ? 1 : 2) : 0;
            #pragma unroll
            for (int s = 0; s < 4; ++s) {
                const bool a0on = !wx3 || ((s & 1) == 0);
                const bool a1on = !wx3 || ((s & 1) == 1);
                unsigned pas[2][4];
                #pragma unroll
                for (int at = 0; at < 2; ++at) {
                    if ((at == 0 && !a0on) || (at == 1 && !a1on)) continue;
                    #pragma unroll
                    for (int tt = 0; tt < 2; ++tt) {
                        const int t = 2 * s + tt;
                        const int krh = (t < 4) ? krhA : krhB;
                        const float bb = (krh == qrh_all) ? 0.f : MASKB;
                        float p0 = ex2f(fmaf(acc[at][t][0], ISL2, bb));
                        float p1 = ex2f(fmaf(acc[at][t][1], ISL2, bb));
                        float p2 = ex2f(fmaf(acc[at][t][2], ISL2, bb));
                        float p3 = ex2f(fmaf(acc[at][t][3], ISL2, bb));
                        lsum[at][0] += p0 + p1;
                        lsum[at][1] += p2 + p3;
                        pas[at][2 * tt]     = h2u(__floats2half2_rn(p0, p1));
                        pas[at][2 * tt + 1] = h2u(__floats2half2_rn(p2, p3));
                    }
                }
                #pragma unroll
                for (int cp = 0; cp < 8; ++cp) {
                    unsigned b0, b1, b2, b3;
                    LDSM_X4_T(b0, b1, b2, b3, v_lds + s * (16 * STRB) + cp * 32);
                    if (a0on) {
                        mma_f16(o[0][2*cp][0], o[0][2*cp][1], o[0][2*cp][2], o[0][2*cp][3],
                                pas[0][0], pas[0][1], pas[0][2], pas[0][3], b0, b1);
                        mma_f16(o[0][2*cp+1][0], o[0][2*cp+1][1], o[0][2*cp+1][2], o[0][2*cp+1][3],
                                pas[0][0], pas[0][1], pas[0][2], pas[0][3], b2, b3);
                    }
                    if (a1on) {
                        mma_f16(o[1][2*cp][0], o[1][2*cp][1], o[1][2*cp][2], o[1][2*cp][3],
                                pas[1][0], pas[1][1], pas[1][2], pas[1][3], b0, b1);
                        mma_f16(o[1][2*cp+1][0], o[1][2*cp+1][1], o[1][2*cp+1][2], o[1][2*cp+1][3],
                                pas[1][0], pas[1][1], pas[1][2], pas[1][3], b2, b3);
                    }
                }
            }
        }
        __syncthreads();   // all warps done with f16 buffer before next conversion
    }

    // ---- finish row sums + epilogue ----
    #pragma unroll
    for (int at = 0; at < 2; ++at) {
        float llo = lsum[at][0], lhi = lsum[at][1];
        llo += __shfl_xor_sync(0xffffffffu, llo, 1);
        llo += __shfl_xor_sync(0xffffffffu, llo, 2);
        lhi += __shfl_xor_sync(0xffffffffu, lhi, 1);
        lhi += __shfl_xor_sync(0xffffffffu, lhi, 2);
        const int tok_lo = qbase + warp * 32 + at * 16 + lr;
        const int gr_lo = grow_idx(b, wy, wx, tok_lo);
        const int gr_hi = grow_idx(b, wy, wx, tok_lo + 8);
        const float ilo = 1.f / llo;
        const float ihi = 1.f / lhi;
        float* out_lo = out + (size_t)gr_lo * C_DIM + 2 * lc;
        float* out_hi = out + (size_t)gr_hi * C_DIM + 2 * lc;
        #pragma unroll
        for (int t = 0; t < 16; ++t) {
            *reinterpret_cast<float2*>(&out_lo[8 * t]) =
                make_float2(o[at][t][0] * ilo, o[at][t][1] * ilo);
            *reinterpret_cast<float2*>(&out_hi[8 * t]) =
                make_float2(o[at][t][2] * ihi, o[at][t][3] * ihi);
        }
    }
}

extern "C" void kernel_launch(void* const* d_in, const int* in_sizes, int n_in,
                              void* d_out, int out_size) {
    (void)in_sizes; (void)n_in; (void)out_size;
    const float* q = (const float*)d_in[0];
    const float* k = (const float*)d_in[1];
    const float* v = (const float*)d_in[2];
    float* out = (float*)d_out;

    cudaFuncSetAttribute(swin_attn_f16,
                         cudaFuncAttributeMaxDynamicSharedMemorySize, SMEM_BYTES);
    swin_attn_f16<<<dim3(NQT, 8 * 16), 256, SMEM_BYTES>>>(q, k, v, out);
}